// round 13
// baseline (speedup 1.0000x reference)
#include <cuda_runtime.h>
#include <cstddef>
#include <cstdint>

// Problem constants
#define IN_DIM    1024
#define N_NEURONS 1024
#define N_DEND    16
#define NNZ       32
#define N_SOMA    (N_NEURONS * N_DEND)   // 16384
#define BATCH     4096
#define SLOPE     0.1f

// Tiling
#define BT        32       // batches per CTA (lane&7 = batch quad of 4)
#define NPC       64       // neurons per CTA
#define THREADS   512      // 16 warps; quarter-warp = 1 neuron (4 per warp)
#define SO_STRIDE 68

// xs4: float4 rows, 8 quads + 16B pad -> 144 bytes per input-dim row
#define XS4_ROW_BYTES 144
#define XS4_BYTES  (IN_DIM * XS4_ROW_BYTES)     // 147456

// Per (neuron-quad, dendrite) record: 1024B =
//   [OFF q0..q3: 4 x 128B][W q0..q3: 4 x 128B]
// Within quarter q's 128B block, 16B chunk c lives at slot ((c+q)&7)*16
// (bank stagger: one warp-load of chunk c hits 4 distinct bank groups -> 1 wf).
// OFF values are byte offsets i*144 into xs4 (quad slot 0 base).
#define REC4       1024
#define N_QUADS    (N_NEURONS / 4)     // 256
#define WSTAGE     4
#define WRING      (WSTAGE * REC4)     // 4096B per warp

#define WR_BYTES  (16 * WRING)             // 65536
#define MT_BYTES  (NPC * N_DEND * 8)       // 8192
#define SO_BYTES  (BT * SO_STRIDE * 4)     // 8704
#define SMEM_TOTAL (XS4_BYTES + WR_BYTES + MT_BYTES + SO_BYTES)   // 229888

// Device scratch
__device__ __align__(16) unsigned char g_rec[(size_t)N_QUADS * N_DEND * REC4]; // 4MB
__device__ float2 g_meta[N_SOMA];   // (bd[s], ws[s])

#define CP_ASYNC16(dst, src) \
    asm volatile("cp.async.cg.shared.global [%0], [%1], 16;\n" :: "r"(dst), "l"(src))
#define CP_COMMIT() asm volatile("cp.async.commit_group;\n" ::: "memory")
#define CP_WAIT2()  asm volatile("cp.async.wait_group 2;\n" ::: "memory")

// ---------------------------------------------------------------------------
// Preprocess: compact (Wd * dmask) rows into per-(quad,d) 1KB records with
// bank-staggered chunk slots (one warp per soma row); blocks 0..63 also fill
// g_meta. Pure fp32.
// ---------------------------------------------------------------------------
__global__ void prep_kernel(const float* __restrict__ Wd,
                            const float* __restrict__ dmask,
                            const float* __restrict__ Ws,
                            const float* __restrict__ smask,
                            const float* __restrict__ bd) {
    if (blockIdx.x < N_SOMA / 256) {
        int s = blockIdx.x * 256 + threadIdx.x;
        int n = s >> 4;
        size_t o = (size_t)n * N_SOMA + s;
        g_meta[s] = make_float2(bd[s], Ws[o] * smask[o]);
    }
    int s    = blockIdx.x * 8 + (threadIdx.x >> 5);
    int lane = threadIdx.x & 31;
    int n = s >> 4, d = s & 15;
    int quad = n >> 2, sub = n & 3;
    unsigned char* base = g_rec + ((size_t)(quad * N_DEND + d)) * REC4;
    uint32_t* oout = (uint32_t*)(base + sub * 128);
    float*    wout = (float*)(base + 512 + sub * 128);

    const float4* m4   = (const float4*)(dmask + (size_t)s * IN_DIM);
    const float*  wrow = Wd + (size_t)s * IN_DIM;

    int cnt = 0;
    #pragma unroll 2
    for (int c = 0; c < IN_DIM / 128; c++) {
        float4 m = m4[c * 32 + lane];
        float mv[4] = {m.x, m.y, m.z, m.w};
        #pragma unroll
        for (int k = 0; k < 4; k++) {
            bool on = (mv[k] != 0.f);
            unsigned ball = __ballot_sync(0xffffffffu, on);
            if (on) {
                int pos = cnt + __popc(ball & ((1u << lane) - 1u));
                if (pos < NNZ) {
                    int i = c * 128 + lane * 4 + k;
                    // staggered slot: chunk (pos>>2) -> slot ((pos>>2)+sub)&7
                    int idx = ((((pos >> 2) + sub) & 7) << 2) | (pos & 3);
                    wout[idx] = wrow[i] * mv[k];
                    oout[idx] = (uint32_t)(i * XS4_ROW_BYTES);
                }
            }
            cnt += __popc(ball);
        }
    }
}

// ---------------------------------------------------------------------------
// Main fused kernel. Grid (128, 16), 512 threads (16 warps). Warp = neuron
// quad (quarter-warp per neuron), lane&7 = batch quad (float4 of 4 batches).
// Per tap: 1 quad-gather LDS.128 (4-wf byte floor) + 4 FFMA. Weights/offsets
// via bank-staggered quarter-uniform LDS.128 (1 wf) from a warp-private
// 4-stage cp.async ring (stage issued 3 dendrites ahead; wait_group 2).
// Exact fp32.
// ---------------------------------------------------------------------------
__global__ void __launch_bounds__(THREADS, 1)
dend_main(const float* __restrict__ x,
          const float* __restrict__ bs,
          float* __restrict__ out) {
    extern __shared__ char smraw[];
    char*          xs4   = smraw;                                 // [1024][9 f4]
    unsigned char* wring = (unsigned char*)(smraw + XS4_BYTES);   // [16][4][1024]
    float2*        meta  = (float2*)(smraw + XS4_BYTES + WR_BYTES);
    float*         so    = (float*)(smraw + XS4_BYTES + WR_BYTES + MT_BYTES);

    int t = threadIdx.x, lane = t & 31, wid = t >> 5;        // wid 0..15
    int quarter = lane >> 3, q8 = lane & 7;
    int b0 = blockIdx.x * BT;
    int n0 = blockIdx.y * NPC;

    // x tile: 8 batch quads (b0+4q .. b0+4q+3). Warp w owns quad w&7 and
    // input-dim half (w>>3)*512. LDG coalesced; STS.128 at its 4-wf floor.
    {
        int qw = wid & 7;
        int ih = (wid >> 3) * (IN_DIM / 2);
        const float* r0 = x + (size_t)(b0 + 4 * qw) * IN_DIM;
        const float* r1 = r0 + IN_DIM;
        const float* r2 = r1 + IN_DIM;
        const float* r3 = r2 + IN_DIM;
        #pragma unroll 4
        for (int c = 0; c < IN_DIM / 64; c++) {     // 16 iterations
            int i = ih + c * 32 + lane;
            float4 v = make_float4(__ldg(r0 + i), __ldg(r1 + i),
                                   __ldg(r2 + i), __ldg(r3 + i));
            *(float4*)(xs4 + (size_t)i * XS4_ROW_BYTES + qw * 16) = v;
        }
    }
    // meta: 1024 float2, 512 threads load 2 each
    meta[t]       = __ldg(g_meta + (size_t)n0 * N_DEND + t);
    meta[t + 512] = __ldg(g_meta + (size_t)n0 * N_DEND + t + 512);

    // warp-private ring: 1024B per stage, 32 lanes x 2 x 16B
    int myquad = blockIdx.y * 16 + wid;
    const unsigned char* src = g_rec + (size_t)myquad * N_DEND * REC4;
    unsigned char* ring = wring + wid * WRING;
    uint32_t ring_u32 = (uint32_t)__cvta_generic_to_shared(ring);

    #pragma unroll
    for (int s = 0; s < WSTAGE - 1; s++) {          // prologue: stages 0,1,2
        CP_ASYNC16(ring_u32 + s * REC4 + lane * 16,
                   src + (size_t)s * REC4 + lane * 16);
        CP_ASYNC16(ring_u32 + s * REC4 + 512 + lane * 16,
                   src + (size_t)s * REC4 + 512 + lane * 16);
        CP_COMMIT();
    }

    int myn = wid * 4 + quarter;                    // local neuron 0..63
    float accb = __ldg(&bs[n0 + myn]);
    float acc0 = accb, acc1 = accb, acc2 = accb, acc3 = accb;  // 4 batches
    const char* __restrict__ xq = xs4 + q8 * 16;    // per-lane gather base

    // staggered chunk byte-offsets for my quarter: chunk c -> ((c+quarter)&7)*16
    int rot[8];
    #pragma unroll
    for (int c = 0; c < 8; c++) rot[c] = ((c + quarter) & 7) * 16;

    __syncthreads();   // xs4 + meta visible

    #pragma unroll 1
    for (int d = 0; d < N_DEND; d++) {
        // groups committed so far: 0..d+2 (stages 0..d+2). Allow 2 pending
        // (stages d+1, d+2) -> stage d complete.
        CP_WAIT2();
        __syncwarp();      // all lanes done with iter d-1; stage d visible
        // issue stage d+3 into slot (d+3)&3 = (d-1)&3 (consumers passed above)
        if (d + WSTAGE - 1 < N_DEND) {
            uint32_t dsts = ring_u32 + ((d + WSTAGE - 1) & (WSTAGE - 1)) * REC4;
            const unsigned char* srcs = src + (size_t)(d + WSTAGE - 1) * REC4;
            CP_ASYNC16(dsts + lane * 16,       srcs + lane * 16);
            CP_ASYNC16(dsts + 512 + lane * 16, srcs + 512 + lane * 16);
        }
        CP_COMMIT();       // empty group in tail keeps wait arithmetic uniform

        const unsigned char* bufb = ring + (d & (WSTAGE - 1)) * REC4;
        const unsigned char* offp = bufb + quarter * 128;        // my off block
        const unsigned char* wp   = bufb + 512 + quarter * 128;  // my w block
        float2 mt = meta[myn * N_DEND + d];

        // 8 chains: cA (even taps) seeded with bd, cB (odd taps) zero
        float cA0 = mt.x, cA1 = mt.x, cA2 = mt.x, cA3 = mt.x;
        float cB0 = 0.f,  cB1 = 0.f,  cB2 = 0.f,  cB3 = 0.f;
        #pragma unroll
        for (int g = 0; g < 4; g++) {
            uint4  oa = *(const uint4*) (offp + rot[2 * g]);
            uint4  ob = *(const uint4*) (offp + rot[2 * g + 1]);
            float4 wa = *(const float4*)(wp   + rot[2 * g]);
            float4 wb = *(const float4*)(wp   + rot[2 * g + 1]);
            float4 v;
            v = *(const float4*)(xq + oa.x);
            cA0 = fmaf(wa.x, v.x, cA0); cA1 = fmaf(wa.x, v.y, cA1);
            cA2 = fmaf(wa.x, v.z, cA2); cA3 = fmaf(wa.x, v.w, cA3);
            v = *(const float4*)(xq + oa.y);
            cB0 = fmaf(wa.y, v.x, cB0); cB1 = fmaf(wa.y, v.y, cB1);
            cB2 = fmaf(wa.y, v.z, cB2); cB3 = fmaf(wa.y, v.w, cB3);
            v = *(const float4*)(xq + oa.z);
            cA0 = fmaf(wa.z, v.x, cA0); cA1 = fmaf(wa.z, v.y, cA1);
            cA2 = fmaf(wa.z, v.z, cA2); cA3 = fmaf(wa.z, v.w, cA3);
            v = *(const float4*)(xq + oa.w);
            cB0 = fmaf(wa.w, v.x, cB0); cB1 = fmaf(wa.w, v.y, cB1);
            cB2 = fmaf(wa.w, v.z, cB2); cB3 = fmaf(wa.w, v.w, cB3);
            v = *(const float4*)(xq + ob.x);
            cA0 = fmaf(wb.x, v.x, cA0); cA1 = fmaf(wb.x, v.y, cA1);
            cA2 = fmaf(wb.x, v.z, cA2); cA3 = fmaf(wb.x, v.w, cA3);
            v = *(const float4*)(xq + ob.y);
            cB0 = fmaf(wb.y, v.x, cB0); cB1 = fmaf(wb.y, v.y, cB1);
            cB2 = fmaf(wb.y, v.z, cB2); cB3 = fmaf(wb.y, v.w, cB3);
            v = *(const float4*)(xq + ob.z);
            cA0 = fmaf(wb.z, v.x, cA0); cA1 = fmaf(wb.z, v.y, cA1);
            cA2 = fmaf(wb.z, v.z, cA2); cA3 = fmaf(wb.z, v.w, cA3);
            v = *(const float4*)(xq + ob.w);
            cB0 = fmaf(wb.w, v.x, cB0); cB1 = fmaf(wb.w, v.y, cB1);
            cB2 = fmaf(wb.w, v.z, cB2); cB3 = fmaf(wb.w, v.w, cB3);
        }
        float h0 = cA0 + cB0, h1 = cA1 + cB1, h2 = cA2 + cB2, h3 = cA3 + cB3;
        h0 = fmaxf(h0, 0.f) + SLOPE * fminf(h0, 0.f);
        h1 = fmaxf(h1, 0.f) + SLOPE * fminf(h1, 0.f);
        h2 = fmaxf(h2, 0.f) + SLOPE * fminf(h2, 0.f);
        h3 = fmaxf(h3, 0.f) + SLOPE * fminf(h3, 0.f);
        acc0 = fmaf(mt.y, h0, acc0);
        acc1 = fmaf(mt.y, h1, acc1);
        acc2 = fmaf(mt.y, h2, acc2);
        acc3 = fmaf(mt.y, h3, acc3);
    }

    // stage outputs: batches b0+4*q8+j, neuron myn
    {
        float o;
        o = fmaxf(acc0, 0.f) + SLOPE * fminf(acc0, 0.f); so[(4 * q8 + 0) * SO_STRIDE + myn] = o;
        o = fmaxf(acc1, 0.f) + SLOPE * fminf(acc1, 0.f); so[(4 * q8 + 1) * SO_STRIDE + myn] = o;
        o = fmaxf(acc2, 0.f) + SLOPE * fminf(acc2, 0.f); so[(4 * q8 + 2) * SO_STRIDE + myn] = o;
        o = fmaxf(acc3, 0.f) + SLOPE * fminf(acc3, 0.f); so[(4 * q8 + 3) * SO_STRIDE + myn] = o;
    }
    __syncthreads();

    // coalesced output: 32 rows x 64 cols, 512 threads write one float4 each
    {
        int b = t >> 4, c = (t & 15) * 4;
        float4 v = *(const float4*)&so[b * SO_STRIDE + c];
        *(float4*)&out[(size_t)(b0 + b) * N_NEURONS + n0 + c] = v;
    }
}

// ---------------------------------------------------------------------------
// Launch. Inputs (metadata order): x, Wd, bd, Ws, bs, dendrite_mask, soma_mask
// ---------------------------------------------------------------------------
extern "C" void kernel_launch(void* const* d_in, const int* in_sizes, int n_in,
                              void* d_out, int out_size) {
    const float* x     = (const float*)d_in[0];
    const float* Wd    = (const float*)d_in[1];
    const float* bd    = (const float*)d_in[2];
    const float* Ws    = (const float*)d_in[3];
    const float* bs    = (const float*)d_in[4];
    const float* dmask = (const float*)d_in[5];
    const float* smask = (const float*)d_in[6];
    float* out = (float*)d_out;

    cudaFuncSetAttribute(dend_main,
                         cudaFuncAttributeMaxDynamicSharedMemorySize, SMEM_TOTAL);

    prep_kernel<<<N_SOMA / 8, 256>>>(Wd, dmask, Ws, smask, bd);

    dim3 grid(BATCH / BT, N_NEURONS / NPC);   // (128, 16)
    dend_main<<<grid, THREADS, SMEM_TOTAL>>>(x, bs, out);
}

// round 14
// speedup vs baseline: 1.0771x; 1.0771x over previous
#include <cuda_runtime.h>
#include <cstddef>
#include <cstdint>

// Problem constants
#define IN_DIM    1024
#define N_NEURONS 1024
#define N_DEND    16
#define NNZ       32
#define N_SOMA    (N_NEURONS * N_DEND)   // 16384
#define BATCH     4096
#define SLOPE     0.1f

// Tiling
#define BT        32       // batches per CTA (lane&7 = batch quad of 4)
#define NPC       128      // neurons per CTA (2 quads per warp, sequential)
#define THREADS   512      // 16 warps; quarter-warp = 1 neuron slot
#define SO_STRIDE 132      // out staging stride (floats, rows 16B aligned)

// xs4: float4 rows, 8 quads + 16B pad -> 144 bytes per input-dim row
#define XS4_ROW_BYTES 144
#define XS4_BYTES  (IN_DIM * XS4_ROW_BYTES)     // 147456

// Per (neuron-quad, dendrite) record: 1024B =
//   [OFF q0..q3: 4 x 128B][W q0..q3: 4 x 128B]
// Within quarter q's 128B block, 16B chunk c lives at slot ((c+q)&7)*16
// (bank stagger: warp-load of chunk c hits 4 distinct bank groups -> 1 wf).
// OFF values are byte offsets i*144 into xs4 (quad slot 0 base).
#define REC4       1024
#define N_QUADS    (N_NEURONS / 4)     // 256
#define WSTAGE     3
#define WRING      (WSTAGE * REC4)     // 3072B per warp
#define NSTAGES    32                  // 2 quads x 16 dendrites per warp

#define WR_BYTES  (16 * WRING)             // 49152
#define MT_BYTES  (NPC * N_DEND * 8)       // 16384
#define SO_BYTES  (BT * SO_STRIDE * 4)     // 16896
#define SMEM_TOTAL (XS4_BYTES + WR_BYTES + MT_BYTES + SO_BYTES)   // 229888

// Device scratch
__device__ __align__(16) unsigned char g_rec[(size_t)N_QUADS * N_DEND * REC4]; // 4MB
__device__ float2 g_meta[N_SOMA];   // (bd[s], ws[s])

#define CP_ASYNC16(dst, src) \
    asm volatile("cp.async.cg.shared.global [%0], [%1], 16;\n" :: "r"(dst), "l"(src))
#define CP_COMMIT() asm volatile("cp.async.commit_group;\n" ::: "memory")
#define CP_WAIT1()  asm volatile("cp.async.wait_group 1;\n" ::: "memory")

// ---------------------------------------------------------------------------
// Preprocess: per-lane bitmask + warp scan compaction (no serial ballots).
// One warp per soma row; order within a row is lane-major (irrelevant for a
// dot product; mask values are exactly 1.0). Blocks 0..63 also fill g_meta.
// ---------------------------------------------------------------------------
__global__ void prep_kernel(const float* __restrict__ Wd,
                            const float* __restrict__ dmask,
                            const float* __restrict__ Ws,
                            const float* __restrict__ smask,
                            const float* __restrict__ bd) {
    if (blockIdx.x < N_SOMA / 256) {
        int s = blockIdx.x * 256 + threadIdx.x;
        int n = s >> 4;
        size_t o = (size_t)n * N_SOMA + s;
        g_meta[s] = make_float2(bd[s], Ws[o] * smask[o]);
    }
    int s    = blockIdx.x * 8 + (threadIdx.x >> 5);
    int lane = threadIdx.x & 31;
    int n = s >> 4, d = s & 15;
    int quad = n >> 2, sub = n & 3;
    unsigned char* base_p = g_rec + ((size_t)(quad * N_DEND + d)) * REC4;
    uint32_t* oout = (uint32_t*)(base_p + sub * 128);
    float*    wout = (float*)(base_p + 512 + sub * 128);

    const float4* m4   = (const float4*)(dmask + (size_t)s * IN_DIM);
    const float*  wrow = Wd + (size_t)s * IN_DIM;

    // bitmask of this lane's 32 elements (i = c*128 + lane*4 + k, bit c*4+k)
    unsigned bm = 0;
    #pragma unroll
    for (int c = 0; c < 8; c++) {
        float4 m = m4[c * 32 + lane];
        bm |= (m.x != 0.f ? 1u : 0u) << (c * 4 + 0);
        bm |= (m.y != 0.f ? 1u : 0u) << (c * 4 + 1);
        bm |= (m.z != 0.f ? 1u : 0u) << (c * 4 + 2);
        bm |= (m.w != 0.f ? 1u : 0u) << (c * 4 + 3);
    }
    int cnt = __popc(bm);
    // inclusive shfl scan -> exclusive base
    int scan = cnt;
    #pragma unroll
    for (int off = 1; off < 32; off <<= 1) {
        int v = __shfl_up_sync(0xffffffffu, scan, off);
        if (lane >= off) scan += v;
    }
    int pos = scan - cnt;   // exclusive prefix
    while (bm) {
        int b = __ffs(bm) - 1;
        bm &= bm - 1;
        if (pos < NNZ) {
            int i = (b >> 2) * 128 + lane * 4 + (b & 3);
            int idx = ((((pos >> 2) + sub) & 7) << 2) | (pos & 3);
            wout[idx] = wrow[i];                       // mask value == 1.0
            oout[idx] = (uint32_t)(i * XS4_ROW_BYTES);
        }
        pos++;
    }
}

// ---------------------------------------------------------------------------
// Main fused kernel. Grid (128, 8), 512 threads (16 warps). Warp = 2 neuron
// quads processed sequentially (quarter-warp per neuron), lane&7 = batch quad
// (float4 of 4 batches). Per tap: 1 quad-gather LDS.128 (4-wf byte floor) +
// 4 FFMA. Weights/offsets via bank-staggered quarter-uniform LDS.128 (1 wf)
// from a warp-private 3-stage cp.async ring streaming 32 stages. Exact fp32.
// ---------------------------------------------------------------------------
__global__ void __launch_bounds__(THREADS, 1)
dend_main(const float* __restrict__ x,
          const float* __restrict__ bs,
          float* __restrict__ out) {
    extern __shared__ char smraw[];
    char*          xs4   = smraw;                                 // [1024][9 f4]
    unsigned char* wring = (unsigned char*)(smraw + XS4_BYTES);   // [16][3][1024]
    float2*        meta  = (float2*)(smraw + XS4_BYTES + WR_BYTES);
    float*         so    = (float*)(smraw + XS4_BYTES + WR_BYTES + MT_BYTES);

    int t = threadIdx.x, lane = t & 31, wid = t >> 5;        // wid 0..15
    int quarter = lane >> 3, q8 = lane & 7;
    int b0 = blockIdx.x * BT;
    int n0 = blockIdx.y * NPC;

    // x tile: 8 batch quads (b0+4q .. b0+4q+3). Warp w owns quad w&7 and
    // input-dim half (w>>3)*512. LDG coalesced; STS.128 at its 4-wf floor.
    {
        int qw = wid & 7;
        int ih = (wid >> 3) * (IN_DIM / 2);
        const float* r0 = x + (size_t)(b0 + 4 * qw) * IN_DIM;
        const float* r1 = r0 + IN_DIM;
        const float* r2 = r1 + IN_DIM;
        const float* r3 = r2 + IN_DIM;
        #pragma unroll 4
        for (int c = 0; c < IN_DIM / 64; c++) {     // 16 iterations
            int i = ih + c * 32 + lane;
            float4 v = make_float4(__ldg(r0 + i), __ldg(r1 + i),
                                   __ldg(r2 + i), __ldg(r3 + i));
            *(float4*)(xs4 + (size_t)i * XS4_ROW_BYTES + qw * 16) = v;
        }
    }
    // meta: 2048 float2, 512 threads load 4 each (coalesced)
    #pragma unroll
    for (int r = 0; r < 4; r++)
        meta[r * 512 + t] = __ldg(g_meta + (size_t)n0 * N_DEND + r * 512 + t);

    // two quads per warp: qA = by*32 + wid, qB = qA + 16
    const unsigned char* srcA = g_rec + (size_t)(blockIdx.y * 32 + wid) * N_DEND * REC4;
    const unsigned char* srcB = srcA + (size_t)16 * N_DEND * REC4;
    unsigned char* ring = wring + wid * WRING;
    uint32_t ring_u32 = (uint32_t)__cvta_generic_to_shared(ring);

    // stage s (0..31): quad s>>4, dendrite s&15
    #pragma unroll
    for (int s = 0; s < WSTAGE - 1; s++) {          // prologue: stages 0,1
        const unsigned char* sp = srcA + (size_t)s * REC4;   // s<16 always here
        CP_ASYNC16(ring_u32 + s * REC4 + lane * 16,       sp + lane * 16);
        CP_ASYNC16(ring_u32 + s * REC4 + 512 + lane * 16, sp + 512 + lane * 16);
        CP_COMMIT();
    }

    const char* __restrict__ xq = xs4 + q8 * 16;    // per-lane gather base

    // staggered chunk byte-offsets: chunk c -> ((c+quarter)&7)*16
    int rot[8];
    #pragma unroll
    for (int c = 0; c < 8; c++) rot[c] = ((c + quarter) & 7) * 16;

    __syncthreads();   // xs4 + meta visible

    #pragma unroll 1
    for (int qsel = 0; qsel < 2; qsel++) {
        int myn = wid * 4 + quarter + qsel * 64;    // local neuron 0..127
        float accb = __ldg(&bs[n0 + myn]);
        float acc0 = accb, acc1 = accb, acc2 = accb, acc3 = accb;

        #pragma unroll 1
        for (int d = 0; d < N_DEND; d++) {
            int s = qsel * 16 + d;
            // committed groups: 0..s+1; wait_group 1 -> stages 0..s done
            CP_WAIT1();
            __syncwarp();   // all lanes finished stage s-1 compute; slot free
            int sf = s + WSTAGE - 1;                // stage to fetch (slot (s-1)%3)
            if (sf < NSTAGES) {
                const unsigned char* sp = (sf < 16)
                    ? srcA + (size_t)sf * REC4
                    : srcB + (size_t)(sf - 16) * REC4;
                uint32_t dsts = ring_u32 + (sf % WSTAGE) * REC4;
                CP_ASYNC16(dsts + lane * 16,       sp + lane * 16);
                CP_ASYNC16(dsts + 512 + lane * 16, sp + 512 + lane * 16);
            }
            CP_COMMIT();    // empty group in tail keeps wait arithmetic uniform

            const unsigned char* bufb = ring + (s % WSTAGE) * REC4;
            const unsigned char* offp = bufb + quarter * 128;
            const unsigned char* wp   = bufb + 512 + quarter * 128;
            float2 mt = meta[myn * N_DEND + d];

            float cA0 = mt.x, cA1 = mt.x, cA2 = mt.x, cA3 = mt.x;
            float cB0 = 0.f,  cB1 = 0.f,  cB2 = 0.f,  cB3 = 0.f;
            #pragma unroll
            for (int g = 0; g < 4; g++) {
                uint4  oa = *(const uint4*) (offp + rot[2 * g]);
                uint4  ob = *(const uint4*) (offp + rot[2 * g + 1]);
                float4 wa = *(const float4*)(wp   + rot[2 * g]);
                float4 wb = *(const float4*)(wp   + rot[2 * g + 1]);
                float4 v;
                v = *(const float4*)(xq + oa.x);
                cA0 = fmaf(wa.x, v.x, cA0); cA1 = fmaf(wa.x, v.y, cA1);
                cA2 = fmaf(wa.x, v.z, cA2); cA3 = fmaf(wa.x, v.w, cA3);
                v = *(const float4*)(xq + oa.y);
                cB0 = fmaf(wa.y, v.x, cB0); cB1 = fmaf(wa.y, v.y, cB1);
                cB2 = fmaf(wa.y, v.z, cB2); cB3 = fmaf(wa.y, v.w, cB3);
                v = *(const float4*)(xq + oa.z);
                cA0 = fmaf(wa.z, v.x, cA0); cA1 = fmaf(wa.z, v.y, cA1);
                cA2 = fmaf(wa.z, v.z, cA2); cA3 = fmaf(wa.z, v.w, cA3);
                v = *(const float4*)(xq + oa.w);
                cB0 = fmaf(wa.w, v.x, cB0); cB1 = fmaf(wa.w, v.y, cB1);
                cB2 = fmaf(wa.w, v.z, cB2); cB3 = fmaf(wa.w, v.w, cB3);
                v = *(const float4*)(xq + ob.x);
                cA0 = fmaf(wb.x, v.x, cA0); cA1 = fmaf(wb.x, v.y, cA1);
                cA2 = fmaf(wb.x, v.z, cA2); cA3 = fmaf(wb.x, v.w, cA3);
                v = *(const float4*)(xq + ob.y);
                cB0 = fmaf(wb.y, v.x, cB0); cB1 = fmaf(wb.y, v.y, cB1);
                cB2 = fmaf(wb.y, v.z, cB2); cB3 = fmaf(wb.y, v.w, cB3);
                v = *(const float4*)(xq + ob.z);
                cA0 = fmaf(wb.z, v.x, cA0); cA1 = fmaf(wb.z, v.y, cA1);
                cA2 = fmaf(wb.z, v.z, cA2); cA3 = fmaf(wb.z, v.w, cA3);
                v = *(const float4*)(xq + ob.w);
                cB0 = fmaf(wb.w, v.x, cB0); cB1 = fmaf(wb.w, v.y, cB1);
                cB2 = fmaf(wb.w, v.z, cB2); cB3 = fmaf(wb.w, v.w, cB3);
            }
            float h0 = cA0 + cB0, h1 = cA1 + cB1, h2 = cA2 + cB2, h3 = cA3 + cB3;
            h0 = fmaxf(h0, 0.f) + SLOPE * fminf(h0, 0.f);
            h1 = fmaxf(h1, 0.f) + SLOPE * fminf(h1, 0.f);
            h2 = fmaxf(h2, 0.f) + SLOPE * fminf(h2, 0.f);
            h3 = fmaxf(h3, 0.f) + SLOPE * fminf(h3, 0.f);
            acc0 = fmaf(mt.y, h0, acc0);
            acc1 = fmaf(mt.y, h1, acc1);
            acc2 = fmaf(mt.y, h2, acc2);
            acc3 = fmaf(mt.y, h3, acc3);
        }

        float o;
        o = fmaxf(acc0, 0.f) + SLOPE * fminf(acc0, 0.f); so[(4 * q8 + 0) * SO_STRIDE + myn] = o;
        o = fmaxf(acc1, 0.f) + SLOPE * fminf(acc1, 0.f); so[(4 * q8 + 1) * SO_STRIDE + myn] = o;
        o = fmaxf(acc2, 0.f) + SLOPE * fminf(acc2, 0.f); so[(4 * q8 + 2) * SO_STRIDE + myn] = o;
        o = fmaxf(acc3, 0.f) + SLOPE * fminf(acc3, 0.f); so[(4 * q8 + 3) * SO_STRIDE + myn] = o;
    }
    __syncthreads();

    // coalesced output: 32 rows x 128 cols = 1024 float4, 512 threads x 2
    #pragma unroll
    for (int r = 0; r < 2; r++) {
        int e = r * 512 + t;
        int b = e >> 5, c = (e & 31) * 4;
        float4 v = *(const float4*)&so[b * SO_STRIDE + c];
        *(float4*)&out[(size_t)(b0 + b) * N_NEURONS + n0 + c] = v;
    }
}

// ---------------------------------------------------------------------------
// Launch. Inputs (metadata order): x, Wd, bd, Ws, bs, dendrite_mask, soma_mask
// ---------------------------------------------------------------------------
extern "C" void kernel_launch(void* const* d_in, const int* in_sizes, int n_in,
                              void* d_out, int out_size) {
    const float* x     = (const float*)d_in[0];
    const float* Wd    = (const float*)d_in[1];
    const float* bd    = (const float*)d_in[2];
    const float* Ws    = (const float*)d_in[3];
    const float* bs    = (const float*)d_in[4];
    const float* dmask = (const float*)d_in[5];
    const float* smask = (const float*)d_in[6];
    float* out = (float*)d_out;

    cudaFuncSetAttribute(dend_main,
                         cudaFuncAttributeMaxDynamicSharedMemorySize, SMEM_TOTAL);

    prep_kernel<<<N_SOMA / 8, 256>>>(Wd, dmask, Ws, smask, bd);

    dim3 grid(BATCH / BT, N_NEURONS / NPC);   // (128, 8)
    dend_main<<<grid, THREADS, SMEM_TOTAL>>>(x, bs, out);
}